// round 2
// baseline (speedup 1.0000x reference)
#include <cuda_runtime.h>
#include <math.h>
#include <stdint.h>

// ---------------- problem constants ----------------
constexpr int cB = 1024;
constexpr int cS = 10;
constexpr int cN = 36;
constexpr int cF = 2048;
constexpr int cD = 2176;
constexpr int cH = 2176;
constexpr int BSr = cB * cS;   // 10240 slot rows
constexpr int BNr = cB * cN;   // 36864 pano rows
constexpr int G3  = 3 * cF;    // 6144

// ---------------- scratch (device globals; allocation-free rule) -----------
__device__ float g_pano[(size_t)BNr * cD];
__device__ float g_k   [(size_t)BNr * cD];
__device__ float g_v   [(size_t)BNr * cD];
__device__ float g_s   [(size_t)BSr * cD];
__device__ float g_q   [(size_t)BSr * cD];
__device__ float g_upd [(size_t)BSr * cD];
__device__ float g_gi  [(size_t)BSr * G3];
__device__ float g_gh  [(size_t)BSr * G3];
__device__ float g_h   [(size_t)BSr * cF];
__device__ float g_hnew[(size_t)BSr * cF];
__device__ float g_pre [(size_t)BSr * cF];
__device__ float g_hid [(size_t)BSr * cH];
__device__ float g_attn[(size_t)BSr * cN];
__device__ int   g_mask_mode;   // 0 = u8 bool, 1 = int32, 2 = float32

// ---------------- mask dtype detection ----------------
__global__ void detect_mask_k(const unsigned char* __restrict__ m) {
    __shared__ int c1, c3f;
    if (threadIdx.x == 0) { c1 = 0; c3f = 0; }
    __syncthreads();
    int l1 = 0, l3 = 0;
    for (int i = threadIdx.x; i < BSr; i += 256) {
        unsigned char v = m[i];
        if ((i & 3) != 0 && v == 1) l1++;
        if (v == 0x3f) l3++;
    }
    atomicAdd(&c1, l1);
    atomicAdd(&c3f, l3);
    __syncthreads();
    if (threadIdx.x == 0) g_mask_mode = (c3f > 0) ? 2 : (c1 > 0 ? 0 : 1);
}

// ---------------- generic LayerNorm over width cF ----------------
// x row-major with stride xs; y with stride ys. Optional 128-elem tail copy
// from tailsrc (stride cD, offset cF) into y[cF..cD).
template <bool TAIL>
__global__ void __launch_bounds__(256) ln_k(
    const float* __restrict__ x, long long xs,
    float* __restrict__ y, long long ys,
    const float* __restrict__ gam, const float* __restrict__ bet,
    const float* __restrict__ tailsrc)
{
    const int row = blockIdx.x;
    const float* xr = x + (size_t)row * xs;
    float* yr = y + (size_t)row * ys;
    const int tid = threadIdx.x;

    float s = 0.f, s2 = 0.f;
    for (int c = tid * 4; c < cF; c += 1024) {
        float4 v = *reinterpret_cast<const float4*>(xr + c);
        s  += v.x + v.y + v.z + v.w;
        s2 += v.x * v.x + v.y * v.y + v.z * v.z + v.w * v.w;
    }
    #pragma unroll
    for (int o = 16; o; o >>= 1) {
        s  += __shfl_xor_sync(0xffffffffu, s,  o);
        s2 += __shfl_xor_sync(0xffffffffu, s2, o);
    }
    __shared__ float ws[8], ws2[8];
    const int warp = tid >> 5, lane = tid & 31;
    if (lane == 0) { ws[warp] = s; ws2[warp] = s2; }
    __syncthreads();
    if (tid == 0) {
        float a = 0.f, b2 = 0.f;
        #pragma unroll
        for (int w = 0; w < 8; w++) { a += ws[w]; b2 += ws2[w]; }
        ws[0] = a; ws2[0] = b2;
    }
    __syncthreads();
    const float mean = ws[0] * (1.f / cF);
    const float var  = ws2[0] * (1.f / cF) - mean * mean;
    const float rstd = rsqrtf(var + 1e-5f);

    for (int c = tid * 4; c < cF; c += 1024) {
        float4 v = *reinterpret_cast<const float4*>(xr + c);
        float4 g4 = *reinterpret_cast<const float4*>(gam + c);
        float4 b4 = *reinterpret_cast<const float4*>(bet + c);
        float4 o4;
        o4.x = (v.x - mean) * rstd * g4.x + b4.x;
        o4.y = (v.y - mean) * rstd * g4.y + b4.y;
        o4.z = (v.z - mean) * rstd * g4.z + b4.z;
        o4.w = (v.w - mean) * rstd * g4.w + b4.w;
        *reinterpret_cast<float4*>(yr + c) = o4;
    }
    if (TAIL) {
        if (tid < cD - cF)
            yr[cF + tid] = tailsrc[(size_t)row * cD + cF + tid];
    }
}

// ---------------- SGEMM: C[M,Nc] = A[M,K] @ W[Nc,K]^T (+bias, relu, add) ---
// Tiles: 128x128x16, 256 threads, 8x8 per-thread microtile.
// All call sites have M%128==0, Nc%128==0, K%16==0: no bounds checks.
template <bool RELU, bool ADD>
__global__ void __launch_bounds__(256) sgemm_k(
    const float* __restrict__ A, const float* __restrict__ W,
    const float* __restrict__ bias, const float* __restrict__ addsrc,
    float* __restrict__ C, int M, int Nc, int K)
{
    __shared__ __align__(16) float As[16][128];
    __shared__ __align__(16) float Ws[16][128];

    const int tid = threadIdx.x;
    const int m0 = blockIdx.y * 128;
    const int n0 = blockIdx.x * 128;
    const int tx = tid & 15;
    const int ty = tid >> 4;

    float acc[8][8];
    #pragma unroll
    for (int i = 0; i < 8; i++)
        #pragma unroll
        for (int j = 0; j < 8; j++) acc[i][j] = 0.f;

    for (int kt = 0; kt < K; kt += 16) {
        #pragma unroll
        for (int l = 0; l < 2; l++) {
            const int lin = tid + l * 256;
            const int row = lin >> 2;
            const int kq  = (lin & 3) << 2;
            float4 va = *reinterpret_cast<const float4*>(
                &A[(size_t)(m0 + row) * K + kt + kq]);
            As[kq + 0][row] = va.x; As[kq + 1][row] = va.y;
            As[kq + 2][row] = va.z; As[kq + 3][row] = va.w;
            float4 vw = *reinterpret_cast<const float4*>(
                &W[(size_t)(n0 + row) * K + kt + kq]);
            Ws[kq + 0][row] = vw.x; Ws[kq + 1][row] = vw.y;
            Ws[kq + 2][row] = vw.z; Ws[kq + 3][row] = vw.w;
        }
        __syncthreads();

        #pragma unroll
        for (int k = 0; k < 16; k++) {
            float4 a0 = *reinterpret_cast<const float4*>(&As[k][ty * 4]);
            float4 a1 = *reinterpret_cast<const float4*>(&As[k][64 + ty * 4]);
            float4 b0 = *reinterpret_cast<const float4*>(&Ws[k][tx * 4]);
            float4 b1 = *reinterpret_cast<const float4*>(&Ws[k][64 + tx * 4]);
            float a[8] = {a0.x, a0.y, a0.z, a0.w, a1.x, a1.y, a1.z, a1.w};
            float b[8] = {b0.x, b0.y, b0.z, b0.w, b1.x, b1.y, b1.z, b1.w};
            #pragma unroll
            for (int i = 0; i < 8; i++)
                #pragma unroll
                for (int j = 0; j < 8; j++)
                    acc[i][j] = fmaf(a[i], b[j], acc[i][j]);
        }
        __syncthreads();
    }

    #pragma unroll
    for (int i = 0; i < 8; i++) {
        const int r = m0 + ((i < 4) ? (ty * 4 + i) : (64 + ty * 4 + i - 4));
        #pragma unroll
        for (int half = 0; half < 2; half++) {
            const int c0 = n0 + ((half == 0) ? tx * 4 : 64 + tx * 4);
            float4 o;
            o.x = acc[i][half * 4 + 0];
            o.y = acc[i][half * 4 + 1];
            o.z = acc[i][half * 4 + 2];
            o.w = acc[i][half * 4 + 3];
            if (bias) {
                float4 b4 = *reinterpret_cast<const float4*>(bias + c0);
                o.x += b4.x; o.y += b4.y; o.z += b4.z; o.w += b4.w;
            }
            if (RELU) {
                o.x = fmaxf(o.x, 0.f); o.y = fmaxf(o.y, 0.f);
                o.z = fmaxf(o.z, 0.f); o.w = fmaxf(o.w, 0.f);
            }
            if (ADD) {
                float4 ad = *reinterpret_cast<const float4*>(
                    &addsrc[(size_t)r * Nc + c0]);
                o.x += ad.x; o.y += ad.y; o.z += ad.z; o.w += ad.w;
            }
            *reinterpret_cast<float4*>(&C[(size_t)r * Nc + c0]) = o;
        }
    }
}

// ---------------- attention: dots -> masked softmax(axis=i) -> attn @ v ----
__global__ void __launch_bounds__(256) attn_k(
    const void* __restrict__ mask,
    const float* __restrict__ q, const float* __restrict__ kk,
    const float* __restrict__ vv,
    float* __restrict__ attn_out, float* __restrict__ upd)
{
    const int b = blockIdx.x;
    __shared__ float sd[cS][cN];
    __shared__ float smask[cS];
    const int tid = threadIdx.x;

    if (tid < cS) {
        const int mm = g_mask_mode;
        bool masked;
        const int idx = b * cS + tid;
        if (mm == 0)      masked = ((const unsigned char*)mask)[idx] != 0;
        else if (mm == 1) masked = ((const int*)mask)[idx] != 0;
        else              masked = ((const float*)mask)[idx] != 0.f;
        smask[tid] = masked ? 1.f : 0.f;
    }
    __syncthreads();

    const int warp = tid >> 5, lane = tid & 31;
    const float scale = rsqrtf((float)cD);

    // dots[i][j] = scale * <q[b,i,:], k[b,j,:]>
    for (int p = warp; p < cS * cN; p += 8) {
        const int i = p / cN, j = p % cN;
        const float* qr = q  + (size_t)(b * cS + i) * cD;
        const float* kr = kk + (size_t)(b * cN + j) * cD;
        float sum = 0.f;
        for (int d = lane * 4; d < cD; d += 128) {
            float4 qa = *reinterpret_cast<const float4*>(qr + d);
            float4 ka = *reinterpret_cast<const float4*>(kr + d);
            sum += qa.x * ka.x + qa.y * ka.y + qa.z * ka.z + qa.w * ka.w;
        }
        #pragma unroll
        for (int o = 16; o; o >>= 1) sum += __shfl_xor_sync(0xffffffffu, sum, o);
        if (lane == 0)
            sd[i][j] = (smask[i] > 0.f) ? -INFINITY : sum * scale;
    }
    __syncthreads();

    // softmax over i (slots) per column j
    if (tid < cN) {
        const int j = tid;
        float m = -INFINITY;
        #pragma unroll
        for (int i = 0; i < cS; i++) m = fmaxf(m, sd[i][j]);
        float e[cS];
        float ssum = 0.f;
        #pragma unroll
        for (int i = 0; i < cS; i++) { e[i] = expf(sd[i][j] - m); ssum += e[i]; }
        const float inv = 1.f / ssum;
        #pragma unroll
        for (int i = 0; i < cS; i++) {
            const float a = e[i] * inv;
            sd[i][j] = a;
            attn_out[(size_t)(b * cS + i) * cN + j] = a;
        }
    }
    __syncthreads();

    // updates[i][d] = sum_j attn[i][j] * v[b,j,d]
    for (int d = tid; d < cD; d += 256) {
        float acc[cS];
        #pragma unroll
        for (int i = 0; i < cS; i++) acc[i] = 0.f;
        for (int j = 0; j < cN; j++) {
            const float vj = vv[(size_t)(b * cN + j) * cD + d];
            #pragma unroll
            for (int i = 0; i < cS; i++) acc[i] = fmaf(sd[i][j], vj, acc[i]);
        }
        #pragma unroll
        for (int i = 0; i < cS; i++)
            upd[(size_t)(b * cS + i) * cD + d] = acc[i];
    }
}

// ---------------- GRU elementwise ----------------
__global__ void __launch_bounds__(256) gru_k(
    const float* __restrict__ gi, const float* __restrict__ gh,
    const float* __restrict__ h, float* __restrict__ hnew)
{
    const size_t idx = (size_t)blockIdx.x * 256 + threadIdx.x;  // BSr*cF total
    const int row = (int)(idx / cF);
    const int f   = (int)(idx % cF);
    const size_t o = (size_t)row * G3 + f;
    const float ir = gi[o], iz = gi[o + cF], inn = gi[o + 2 * cF];
    const float hr = gh[o], hz = gh[o + cF], hn  = gh[o + 2 * cF];
    const float hp = h[(size_t)row * cF + f];
    const float r = 1.f / (1.f + expf(-(ir + hr)));
    const float z = 1.f / (1.f + expf(-(iz + hz)));
    const float n = tanhf(inn + r * hn);
    hnew[(size_t)row * cF + f] = (1.f - z) * n + z * hp;
}

// ---------------- init / output ----------------
__global__ void __launch_bounds__(256) init_h_k(
    const float* __restrict__ cand, float* __restrict__ h)
{
    const size_t idx = (size_t)blockIdx.x * 256 + threadIdx.x;  // BSr*cF
    const int row = (int)(idx / cF);
    const int f   = (int)(idx % cF);
    h[idx] = cand[(size_t)row * cD + f];
}

__global__ void __launch_bounds__(256) out_slots_k(
    const float* __restrict__ cand, const float* __restrict__ h,
    float* __restrict__ out)
{
    const size_t idx = (size_t)blockIdx.x * 256 + threadIdx.x;  // BSr*cD
    const int row = (int)(idx / cD);
    const int c   = (int)(idx % cD);
    out[idx] = (c < cF) ? h[(size_t)row * cF + c] : cand[idx];
}

__global__ void __launch_bounds__(256) out_attn_k(
    const float* __restrict__ attn, float* __restrict__ out)
{
    const size_t idx = (size_t)blockIdx.x * 256 + threadIdx.x;  // BSr*cN
    out[(size_t)BSr * cD + idx] = attn[idx];
}

// ---------------- launcher ----------------
extern "C" void kernel_launch(void* const* d_in, const int* in_sizes, int n_in,
                              void* d_out, int out_size)
{
    const float* cand   = (const float*)d_in[0];
    const float* pano   = (const float*)d_in[1];
    const void*  mask   = d_in[2];
    const float* Wq     = (const float*)d_in[3];
    const float* bq     = (const float*)d_in[4];
    const float* Wk     = (const float*)d_in[5];
    const float* bk     = (const float*)d_in[6];
    const float* Wv     = (const float*)d_in[7];
    const float* bv     = (const float*)d_in[8];
    const float* W_ih   = (const float*)d_in[9];
    const float* b_ih   = (const float*)d_in[10];
    const float* W_hh   = (const float*)d_in[11];
    const float* b_hh   = (const float*)d_in[12];
    const float* W1     = (const float*)d_in[13];
    const float* b1     = (const float*)d_in[14];
    const float* W2     = (const float*)d_in[15];
    const float* b2     = (const float*)d_in[16];
    const float* ln_in_g    = (const float*)d_in[17];
    const float* ln_in_b    = (const float*)d_in[18];
    const float* ln_slots_g = (const float*)d_in[19];
    const float* ln_slots_b = (const float*)d_in[20];
    const float* ln_pre_g   = (const float*)d_in[21];
    const float* ln_pre_b   = (const float*)d_in[22];
    float* out = (float*)d_out;

    float *p_pano, *p_k, *p_v, *p_s, *p_q, *p_upd, *p_gi, *p_gh;
    float *p_h, *p_hnew, *p_pre, *p_hid, *p_attn;
    cudaGetSymbolAddress((void**)&p_pano, g_pano);
    cudaGetSymbolAddress((void**)&p_k,    g_k);
    cudaGetSymbolAddress((void**)&p_v,    g_v);
    cudaGetSymbolAddress((void**)&p_s,    g_s);
    cudaGetSymbolAddress((void**)&p_q,    g_q);
    cudaGetSymbolAddress((void**)&p_upd,  g_upd);
    cudaGetSymbolAddress((void**)&p_gi,   g_gi);
    cudaGetSymbolAddress((void**)&p_gh,   g_gh);
    cudaGetSymbolAddress((void**)&p_h,    g_h);
    cudaGetSymbolAddress((void**)&p_hnew, g_hnew);
    cudaGetSymbolAddress((void**)&p_pre,  g_pre);
    cudaGetSymbolAddress((void**)&p_hid,  g_hid);
    cudaGetSymbolAddress((void**)&p_attn, g_attn);

    detect_mask_k<<<1, 256>>>((const unsigned char*)mask);

    // pano LN (+ raw tail) and one-time k, v projections
    ln_k<true><<<BNr, 256>>>(pano, cD, p_pano, cD, ln_in_g, ln_in_b, pano);
    {
        dim3 grid(cD / 128, BNr / 128);
        sgemm_k<false, false><<<grid, 256>>>(p_pano, Wk, bk, nullptr, p_k, BNr, cD, cD);
        sgemm_k<false, false><<<grid, 256>>>(p_pano, Wv, bv, nullptr, p_v, BNr, cD, cD);
    }

    init_h_k<<<(BSr * cF) / 256, 256>>>(cand, p_h);

    for (int it = 0; it < 3; it++) {
        // s = concat(LN(h_prev), angle)
        ln_k<true><<<BSr, 256>>>(p_h, cF, p_s, cD, ln_slots_g, ln_slots_b, cand);
        // q = s @ Wq^T + bq
        {
            dim3 grid(cD / 128, BSr / 128);
            sgemm_k<false, false><<<grid, 256>>>(p_s, Wq, bq, nullptr, p_q, BSr, cD, cD);
        }
        // attention + updates
        attn_k<<<cB, 256>>>(mask, p_q, p_k, p_v, p_attn, p_upd);
        // GRU gates
        {
            dim3 grid(G3 / 128, BSr / 128);
            sgemm_k<false, false><<<grid, 256>>>(p_upd, W_ih, b_ih, nullptr, p_gi, BSr, G3, cD);
            sgemm_k<false, false><<<grid, 256>>>(p_h,   W_hh, b_hh, nullptr, p_gh, BSr, G3, cF);
        }
        gru_k<<<(BSr * cF) / 256, 256>>>(p_gi, p_gh, p_h, p_hnew);
        // pre-LN + MLP, write h = h_new + mlp
        ln_k<false><<<BSr, 256>>>(p_hnew, cF, p_pre, cF, ln_pre_g, ln_pre_b, nullptr);
        {
            dim3 grid1(cH / 128, BSr / 128);
            sgemm_k<true, false><<<grid1, 256>>>(p_pre, W1, b1, nullptr, p_hid, BSr, cH, cF);
            dim3 grid2(cF / 128, BSr / 128);
            sgemm_k<false, true><<<grid2, 256>>>(p_hid, W2, b2, p_hnew, p_h, BSr, cF, cH);
        }
    }

    out_slots_k<<<(BSr * cD) / 256, 256>>>(cand, p_h, out);
    out_attn_k<<<(BSr * cN) / 256, 256>>>(p_attn, out);
}

// round 3
// speedup vs baseline: 1.0002x; 1.0002x over previous
#include <cuda_runtime.h>
#include <math.h>
#include <stdint.h>

// ---------------- problem constants ----------------
constexpr int cB = 1024;
constexpr int cS = 10;
constexpr int cN = 36;
constexpr int cF = 2048;
constexpr int cD = 2176;
constexpr int cH = 2176;
constexpr int BSr = cB * cS;   // 10240 slot rows
constexpr int BNr = cB * cN;   // 36864 pano rows
constexpr int G3  = 3 * cF;    // 6144

// ---------------- scratch (device globals; allocation-free rule) -----------
__device__ float g_pano[(size_t)BNr * cD];
__device__ float g_k   [(size_t)BNr * cD];
__device__ float g_v   [(size_t)BNr * cD];
__device__ float g_s   [(size_t)BSr * cD];
__device__ float g_q   [(size_t)BSr * cD];
__device__ float g_upd [(size_t)BSr * cD];
__device__ float g_gi  [(size_t)BSr * G3];
__device__ float g_gh  [(size_t)BSr * G3];
__device__ float g_h   [(size_t)BSr * cF];
__device__ float g_hnew[(size_t)BSr * cF];
__device__ float g_pre [(size_t)BSr * cF];
__device__ float g_hid [(size_t)BSr * cH];
__device__ float g_attn[(size_t)BSr * cN];
__device__ int   g_mask_mode;   // 0 = u8 bool, 1 = int32, 2 = float32

// ---------------- mask dtype detection ----------------
__global__ void detect_mask_k(const unsigned char* __restrict__ m) {
    __shared__ int c1, c3f;
    if (threadIdx.x == 0) { c1 = 0; c3f = 0; }
    __syncthreads();
    int l1 = 0, l3 = 0;
    for (int i = threadIdx.x; i < BSr; i += 256) {
        unsigned char v = m[i];
        if ((i & 3) != 0 && v == 1) l1++;
        if (v == 0x3f) l3++;
    }
    atomicAdd(&c1, l1);
    atomicAdd(&c3f, l3);
    __syncthreads();
    if (threadIdx.x == 0) g_mask_mode = (c3f > 0) ? 2 : (c1 > 0 ? 0 : 1);
}

// ---------------- generic LayerNorm over width cF ----------------
// x row-major with stride xs; y with stride ys. Optional 128-elem tail copy
// from tailsrc (stride cD, offset cF) into y[cF..cD).
template <bool TAIL>
__global__ void __launch_bounds__(256) ln_k(
    const float* __restrict__ x, long long xs,
    float* __restrict__ y, long long ys,
    const float* __restrict__ gam, const float* __restrict__ bet,
    const float* __restrict__ tailsrc)
{
    const int row = blockIdx.x;
    const float* xr = x + (size_t)row * xs;
    float* yr = y + (size_t)row * ys;
    const int tid = threadIdx.x;

    float s = 0.f, s2 = 0.f;
    for (int c = tid * 4; c < cF; c += 1024) {
        float4 v = *reinterpret_cast<const float4*>(xr + c);
        s  += v.x + v.y + v.z + v.w;
        s2 += v.x * v.x + v.y * v.y + v.z * v.z + v.w * v.w;
    }
    #pragma unroll
    for (int o = 16; o; o >>= 1) {
        s  += __shfl_xor_sync(0xffffffffu, s,  o);
        s2 += __shfl_xor_sync(0xffffffffu, s2, o);
    }
    __shared__ float ws[8], ws2[8];
    const int warp = tid >> 5, lane = tid & 31;
    if (lane == 0) { ws[warp] = s; ws2[warp] = s2; }
    __syncthreads();
    if (tid == 0) {
        float a = 0.f, b2 = 0.f;
        #pragma unroll
        for (int w = 0; w < 8; w++) { a += ws[w]; b2 += ws2[w]; }
        ws[0] = a; ws2[0] = b2;
    }
    __syncthreads();
    const float mean = ws[0] * (1.f / cF);
    const float var  = ws2[0] * (1.f / cF) - mean * mean;
    const float rstd = rsqrtf(var + 1e-5f);

    for (int c = tid * 4; c < cF; c += 1024) {
        float4 v = *reinterpret_cast<const float4*>(xr + c);
        float4 g4 = *reinterpret_cast<const float4*>(gam + c);
        float4 b4 = *reinterpret_cast<const float4*>(bet + c);
        float4 o4;
        o4.x = (v.x - mean) * rstd * g4.x + b4.x;
        o4.y = (v.y - mean) * rstd * g4.y + b4.y;
        o4.z = (v.z - mean) * rstd * g4.z + b4.z;
        o4.w = (v.w - mean) * rstd * g4.w + b4.w;
        *reinterpret_cast<float4*>(yr + c) = o4;
    }
    if (TAIL) {
        if (tid < cD - cF)
            yr[cF + tid] = tailsrc[(size_t)row * cD + cF + tid];
    }
}

// ---------------- SGEMM: C[M,Nc] = A[M,K] @ W[Nc,K]^T (+bias, relu, add) ---
// Tiles: 128x128x16, 256 threads, 8x8 per-thread microtile.
// All call sites have M%128==0, Nc%128==0, K%16==0: no bounds checks.
template <bool RELU, bool ADD>
__global__ void __launch_bounds__(256) sgemm_k(
    const float* __restrict__ A, const float* __restrict__ W,
    const float* __restrict__ bias, const float* __restrict__ addsrc,
    float* __restrict__ C, int M, int Nc, int K)
{
    __shared__ __align__(16) float As[16][128];
    __shared__ __align__(16) float Ws[16][128];

    const int tid = threadIdx.x;
    const int m0 = blockIdx.y * 128;
    const int n0 = blockIdx.x * 128;
    const int tx = tid & 15;
    const int ty = tid >> 4;

    float acc[8][8];
    #pragma unroll
    for (int i = 0; i < 8; i++)
        #pragma unroll
        for (int j = 0; j < 8; j++) acc[i][j] = 0.f;

    for (int kt = 0; kt < K; kt += 16) {
        #pragma unroll
        for (int l = 0; l < 2; l++) {
            const int lin = tid + l * 256;
            const int row = lin >> 2;
            const int kq  = (lin & 3) << 2;
            float4 va = *reinterpret_cast<const float4*>(
                &A[(size_t)(m0 + row) * K + kt + kq]);
            As[kq + 0][row] = va.x; As[kq + 1][row] = va.y;
            As[kq + 2][row] = va.z; As[kq + 3][row] = va.w;
            float4 vw = *reinterpret_cast<const float4*>(
                &W[(size_t)(n0 + row) * K + kt + kq]);
            Ws[kq + 0][row] = vw.x; Ws[kq + 1][row] = vw.y;
            Ws[kq + 2][row] = vw.z; Ws[kq + 3][row] = vw.w;
        }
        __syncthreads();

        #pragma unroll
        for (int k = 0; k < 16; k++) {
            float4 a0 = *reinterpret_cast<const float4*>(&As[k][ty * 4]);
            float4 a1 = *reinterpret_cast<const float4*>(&As[k][64 + ty * 4]);
            float4 b0 = *reinterpret_cast<const float4*>(&Ws[k][tx * 4]);
            float4 b1 = *reinterpret_cast<const float4*>(&Ws[k][64 + tx * 4]);
            float a[8] = {a0.x, a0.y, a0.z, a0.w, a1.x, a1.y, a1.z, a1.w};
            float b[8] = {b0.x, b0.y, b0.z, b0.w, b1.x, b1.y, b1.z, b1.w};
            #pragma unroll
            for (int i = 0; i < 8; i++)
                #pragma unroll
                for (int j = 0; j < 8; j++)
                    acc[i][j] = fmaf(a[i], b[j], acc[i][j]);
        }
        __syncthreads();
    }

    #pragma unroll
    for (int i = 0; i < 8; i++) {
        const int r = m0 + ((i < 4) ? (ty * 4 + i) : (64 + ty * 4 + i - 4));
        #pragma unroll
        for (int half = 0; half < 2; half++) {
            const int c0 = n0 + ((half == 0) ? tx * 4 : 64 + tx * 4);
            float4 o;
            o.x = acc[i][half * 4 + 0];
            o.y = acc[i][half * 4 + 1];
            o.z = acc[i][half * 4 + 2];
            o.w = acc[i][half * 4 + 3];
            if (bias) {
                float4 b4 = *reinterpret_cast<const float4*>(bias + c0);
                o.x += b4.x; o.y += b4.y; o.z += b4.z; o.w += b4.w;
            }
            if (RELU) {
                o.x = fmaxf(o.x, 0.f); o.y = fmaxf(o.y, 0.f);
                o.z = fmaxf(o.z, 0.f); o.w = fmaxf(o.w, 0.f);
            }
            if (ADD) {
                float4 ad = *reinterpret_cast<const float4*>(
                    &addsrc[(size_t)r * Nc + c0]);
                o.x += ad.x; o.y += ad.y; o.z += ad.z; o.w += ad.w;
            }
            *reinterpret_cast<float4*>(&C[(size_t)r * Nc + c0]) = o;
        }
    }
}

// ---------------- attention: dots -> masked softmax(axis=i) -> attn @ v ----
__global__ void __launch_bounds__(256) attn_k(
    const void* __restrict__ mask,
    const float* __restrict__ q, const float* __restrict__ kk,
    const float* __restrict__ vv,
    float* __restrict__ attn_out, float* __restrict__ upd)
{
    const int b = blockIdx.x;
    __shared__ float sd[cS][cN];
    __shared__ float smask[cS];
    const int tid = threadIdx.x;

    if (tid < cS) {
        const int mm = g_mask_mode;
        bool masked;
        const int idx = b * cS + tid;
        if (mm == 0)      masked = ((const unsigned char*)mask)[idx] != 0;
        else if (mm == 1) masked = ((const int*)mask)[idx] != 0;
        else              masked = ((const float*)mask)[idx] != 0.f;
        smask[tid] = masked ? 1.f : 0.f;
    }
    __syncthreads();

    const int warp = tid >> 5, lane = tid & 31;
    const float scale = rsqrtf((float)cD);

    // dots[i][j] = scale * <q[b,i,:], k[b,j,:]>
    for (int p = warp; p < cS * cN; p += 8) {
        const int i = p / cN, j = p % cN;
        const float* qr = q  + (size_t)(b * cS + i) * cD;
        const float* kr = kk + (size_t)(b * cN + j) * cD;
        float sum = 0.f;
        for (int d = lane * 4; d < cD; d += 128) {
            float4 qa = *reinterpret_cast<const float4*>(qr + d);
            float4 ka = *reinterpret_cast<const float4*>(kr + d);
            sum += qa.x * ka.x + qa.y * ka.y + qa.z * ka.z + qa.w * ka.w;
        }
        #pragma unroll
        for (int o = 16; o; o >>= 1) sum += __shfl_xor_sync(0xffffffffu, sum, o);
        if (lane == 0)
            sd[i][j] = (smask[i] > 0.f) ? -INFINITY : sum * scale;
    }
    __syncthreads();

    // softmax over i (slots) per column j
    if (tid < cN) {
        const int j = tid;
        float m = -INFINITY;
        #pragma unroll
        for (int i = 0; i < cS; i++) m = fmaxf(m, sd[i][j]);
        float e[cS];
        float ssum = 0.f;
        #pragma unroll
        for (int i = 0; i < cS; i++) { e[i] = expf(sd[i][j] - m); ssum += e[i]; }
        const float inv = 1.f / ssum;
        #pragma unroll
        for (int i = 0; i < cS; i++) {
            const float a = e[i] * inv;
            sd[i][j] = a;
            attn_out[(size_t)(b * cS + i) * cN + j] = a;
        }
    }
    __syncthreads();

    // updates[i][d] = sum_j attn[i][j] * v[b,j,d]
    for (int d = tid; d < cD; d += 256) {
        float acc[cS];
        #pragma unroll
        for (int i = 0; i < cS; i++) acc[i] = 0.f;
        for (int j = 0; j < cN; j++) {
            const float vj = vv[(size_t)(b * cN + j) * cD + d];
            #pragma unroll
            for (int i = 0; i < cS; i++) acc[i] = fmaf(sd[i][j], vj, acc[i]);
        }
        #pragma unroll
        for (int i = 0; i < cS; i++)
            upd[(size_t)(b * cS + i) * cD + d] = acc[i];
    }
}

// ---------------- GRU elementwise ----------------
__global__ void __launch_bounds__(256) gru_k(
    const float* __restrict__ gi, const float* __restrict__ gh,
    const float* __restrict__ h, float* __restrict__ hnew)
{
    const size_t idx = (size_t)blockIdx.x * 256 + threadIdx.x;  // BSr*cF total
    const int row = (int)(idx / cF);
    const int f   = (int)(idx % cF);
    const size_t o = (size_t)row * G3 + f;
    const float ir = gi[o], iz = gi[o + cF], inn = gi[o + 2 * cF];
    const float hr = gh[o], hz = gh[o + cF], hn  = gh[o + 2 * cF];
    const float hp = h[(size_t)row * cF + f];
    const float r = 1.f / (1.f + expf(-(ir + hr)));
    const float z = 1.f / (1.f + expf(-(iz + hz)));
    const float n = tanhf(inn + r * hn);
    hnew[(size_t)row * cF + f] = (1.f - z) * n + z * hp;
}

// ---------------- init / output ----------------
__global__ void __launch_bounds__(256) init_h_k(
    const float* __restrict__ cand, float* __restrict__ h)
{
    const size_t idx = (size_t)blockIdx.x * 256 + threadIdx.x;  // BSr*cF
    const int row = (int)(idx / cF);
    const int f   = (int)(idx % cF);
    h[idx] = cand[(size_t)row * cD + f];
}

__global__ void __launch_bounds__(256) out_slots_k(
    const float* __restrict__ cand, const float* __restrict__ h,
    float* __restrict__ out)
{
    const size_t idx = (size_t)blockIdx.x * 256 + threadIdx.x;  // BSr*cD
    const int row = (int)(idx / cD);
    const int c   = (int)(idx % cD);
    out[idx] = (c < cF) ? h[(size_t)row * cF + c] : cand[idx];
}

__global__ void __launch_bounds__(256) out_attn_k(
    const float* __restrict__ attn, float* __restrict__ out)
{
    const size_t idx = (size_t)blockIdx.x * 256 + threadIdx.x;  // BSr*cN
    out[(size_t)BSr * cD + idx] = attn[idx];
}

// ---------------- launcher ----------------
extern "C" void kernel_launch(void* const* d_in, const int* in_sizes, int n_in,
                              void* d_out, int out_size)
{
    const float* cand   = (const float*)d_in[0];
    const float* pano   = (const float*)d_in[1];
    const void*  mask   = d_in[2];
    const float* Wq     = (const float*)d_in[3];
    const float* bq     = (const float*)d_in[4];
    const float* Wk     = (const float*)d_in[5];
    const float* bk     = (const float*)d_in[6];
    const float* Wv     = (const float*)d_in[7];
    const float* bv     = (const float*)d_in[8];
    const float* W_ih   = (const float*)d_in[9];
    const float* b_ih   = (const float*)d_in[10];
    const float* W_hh   = (const float*)d_in[11];
    const float* b_hh   = (const float*)d_in[12];
    const float* W1     = (const float*)d_in[13];
    const float* b1     = (const float*)d_in[14];
    const float* W2     = (const float*)d_in[15];
    const float* b2     = (const float*)d_in[16];
    const float* ln_in_g    = (const float*)d_in[17];
    const float* ln_in_b    = (const float*)d_in[18];
    const float* ln_slots_g = (const float*)d_in[19];
    const float* ln_slots_b = (const float*)d_in[20];
    const float* ln_pre_g   = (const float*)d_in[21];
    const float* ln_pre_b   = (const float*)d_in[22];
    float* out = (float*)d_out;

    float *p_pano, *p_k, *p_v, *p_s, *p_q, *p_upd, *p_gi, *p_gh;
    float *p_h, *p_hnew, *p_pre, *p_hid, *p_attn;
    cudaGetSymbolAddress((void**)&p_pano, g_pano);
    cudaGetSymbolAddress((void**)&p_k,    g_k);
    cudaGetSymbolAddress((void**)&p_v,    g_v);
    cudaGetSymbolAddress((void**)&p_s,    g_s);
    cudaGetSymbolAddress((void**)&p_q,    g_q);
    cudaGetSymbolAddress((void**)&p_upd,  g_upd);
    cudaGetSymbolAddress((void**)&p_gi,   g_gi);
    cudaGetSymbolAddress((void**)&p_gh,   g_gh);
    cudaGetSymbolAddress((void**)&p_h,    g_h);
    cudaGetSymbolAddress((void**)&p_hnew, g_hnew);
    cudaGetSymbolAddress((void**)&p_pre,  g_pre);
    cudaGetSymbolAddress((void**)&p_hid,  g_hid);
    cudaGetSymbolAddress((void**)&p_attn, g_attn);

    detect_mask_k<<<1, 256>>>((const unsigned char*)mask);

    // pano LN (+ raw tail) and one-time k, v projections
    ln_k<true><<<BNr, 256>>>(pano, cD, p_pano, cD, ln_in_g, ln_in_b, pano);
    {
        dim3 grid(cD / 128, BNr / 128);
        sgemm_k<false, false><<<grid, 256>>>(p_pano, Wk, bk, nullptr, p_k, BNr, cD, cD);
        sgemm_k<false, false><<<grid, 256>>>(p_pano, Wv, bv, nullptr, p_v, BNr, cD, cD);
    }

    init_h_k<<<(BSr * cF) / 256, 256>>>(cand, p_h);

    for (int it = 0; it < 3; it++) {
        // s = concat(LN(h_prev), angle)
        ln_k<true><<<BSr, 256>>>(p_h, cF, p_s, cD, ln_slots_g, ln_slots_b, cand);
        // q = s @ Wq^T + bq
        {
            dim3 grid(cD / 128, BSr / 128);
            sgemm_k<false, false><<<grid, 256>>>(p_s, Wq, bq, nullptr, p_q, BSr, cD, cD);
        }
        // attention + updates
        attn_k<<<cB, 256>>>(mask, p_q, p_k, p_v, p_attn, p_upd);
        // GRU gates
        {
            dim3 grid(G3 / 128, BSr / 128);
            sgemm_k<false, false><<<grid, 256>>>(p_upd, W_ih, b_ih, nullptr, p_gi, BSr, G3, cD);
            sgemm_k<false, false><<<grid, 256>>>(p_h,   W_hh, b_hh, nullptr, p_gh, BSr, G3, cF);
        }
        gru_k<<<(BSr * cF) / 256, 256>>>(p_gi, p_gh, p_h, p_hnew);
        // pre-LN + MLP, write h = h_new + mlp
        ln_k<false><<<BSr, 256>>>(p_hnew, cF, p_pre, cF, ln_pre_g, ln_pre_b, nullptr);
        {
            dim3 grid1(cH / 128, BSr / 128);
            sgemm_k<true, false><<<grid1, 256>>>(p_pre, W1, b1, nullptr, p_hid, BSr, cH, cF);
            dim3 grid2(cF / 128, BSr / 128);
            sgemm_k<false, true><<<grid2, 256>>>(p_hid, W2, b2, p_hnew, p_h, BSr, cF, cH);
        }
    }

    out_slots_k<<<(BSr * cD) / 256, 256>>>(cand, p_h, out);
    out_attn_k<<<(BSr * cN) / 256, 256>>>(p_attn, out);
}

// round 5
// speedup vs baseline: 2.6942x; 2.6937x over previous
#include <cuda_runtime.h>
#include <cuda_bf16.h>
#include <math.h>
#include <stdint.h>

constexpr int cB = 1024, cS = 10, cN = 36, cF = 2048, cD = 2176;
constexpr int BSr = cB * cS, BNr = cB * cN, G3 = 3 * cF;
constexpr int K3D = 3 * cD, K3F = 3 * cF;        // 6528 / 6144
constexpr int KTD = K3D / 64, KTF = K3F / 64;    // 102 / 96

// fp32 scratch
__device__ float g_k[(size_t)BNr * cD];
__device__ float g_v[(size_t)BNr * cD];
__device__ float g_q[(size_t)BSr * cD];
__device__ float g_upd[(size_t)BSr * cD];
__device__ float g_gi[(size_t)BSr * G3];
__device__ float g_gh[(size_t)BSr * G3];
__device__ float g_h[(size_t)BSr * cF];
__device__ float g_hnew[(size_t)BSr * cF];
__device__ float g_hid[(size_t)BSr * cD];
__device__ float g_attn[(size_t)BSr * cN];
__device__ int g_mask_mode;

// bf16 split operands, pre-swizzled 128x64 16KB tile blocks
__device__ __nv_bfloat16 g_pano_b[(size_t)BNr * K3D];
__device__ __nv_bfloat16 g_s_b [(size_t)BSr * K3D];
__device__ __nv_bfloat16 g_upd_b[(size_t)BSr * K3D];
__device__ __nv_bfloat16 g_h_b [(size_t)BSr * K3F];
__device__ __nv_bfloat16 g_pre_b[(size_t)BSr * K3F];
__device__ __nv_bfloat16 g_hid_b[(size_t)BSr * K3D];
__device__ __nv_bfloat16 g_wq_b [(size_t)2176 * K3D];
__device__ __nv_bfloat16 g_wk_b [(size_t)2176 * K3D];
__device__ __nv_bfloat16 g_wv_b [(size_t)2176 * K3D];
__device__ __nv_bfloat16 g_wih_b[(size_t)6144 * K3D];
__device__ __nv_bfloat16 g_whh_b[(size_t)6144 * K3F];
__device__ __nv_bfloat16 g_w1_b [(size_t)2176 * K3F];
__device__ __nv_bfloat16 g_w2_b [(size_t)2048 * K3D];

__device__ __forceinline__ uint32_t smem_u32(const void* p) {
    uint32_t a;
    asm("{ .reg .u64 t; cvta.to.shared.u64 t, %1; cvt.u32.u64 %0, t; }" : "=r"(a) : "l"(p));
    return a;
}
#define MBAR_INIT(a, c) asm volatile("mbarrier.init.shared.b64 [%0], %1;" :: "r"(a), "r"(c) : "memory")
#define MBAR_EXPECT_TX(a, b) asm volatile("mbarrier.arrive.expect_tx.shared.b64 _, [%0], %1;" :: "r"(a), "r"(b) : "memory")
#define MBAR_WAIT(a, p) do { \
    uint32_t _m = (a), _p = (p), _d; \
    asm volatile("{\n\t.reg .pred q;\n\tmbarrier.try_wait.parity.acquire.cta.shared::cta.b64 q, [%1], %2;\n\tselp.b32 %0, 1, 0, q;\n\t}" \
        : "=r"(_d) : "r"(_m), "r"(_p) : "memory"); \
    if (!_d) { \
        asm volatile("{\n\t.reg .pred P1;\n\tWL_%=:\n\tmbarrier.try_wait.parity.acquire.cta.shared::cta.b64 P1, [%0], %1, 0x989680;\n\t@P1 bra.uni WD_%=;\n\tbra.uni WL_%=;\n\tWD_%=:\n\t}" \
            :: "r"(_m), "r"(_p) : "memory"); \
    } } while (0)

__device__ __forceinline__ void bulk_g2s(uint32_t dst, const void* src, uint32_t bytes, uint32_t mbar) {
    asm volatile("cp.async.bulk.shared::cluster.global.mbarrier::complete_tx::bytes [%0], [%1], %2, [%3];"
        :: "r"(dst), "l"(src), "r"(bytes), "r"(mbar) : "memory");
}

__device__ __forceinline__ uint32_t packbf(float a, float b) {
    return (uint32_t)__bfloat16_as_ushort(__float2bfloat16_rn(a)) |
           ((uint32_t)__bfloat16_as_ushort(__float2bfloat16_rn(b)) << 16);
}
__device__ __forceinline__ float residf(float a) {
    return a - __bfloat162float(__float2bfloat16_rn(a));
}
__device__ __forceinline__ uint32_t swz(uint32_t o) { return o ^ ((o >> 3) & 0x70); }
// 128-row x 64-col bf16 tile blocks (16KB), SW128-swizzled rows of 128B
__device__ __forceinline__ void putA(char* b, int mt, int kt3, int r, int j, uint32_t v) {
    int t = j >> 6, c = j & 63;
    *(uint32_t*)(b + (((size_t)mt * kt3 + t) << 14) + swz((r << 7) + (c << 1))) = v;
}

__global__ void detect_mask_k(const unsigned char* __restrict__ m) {
    __shared__ int c1, c3f;
    if (threadIdx.x == 0) { c1 = 0; c3f = 0; }
    __syncthreads();
    int l1 = 0, l3 = 0;
    for (int i = threadIdx.x; i < BSr; i += 256) {
        unsigned char v = m[i];
        if ((i & 3) != 0 && v == 1) l1++;
        if (v == 0x3f) l3++;
    }
    atomicAdd(&c1, l1); atomicAdd(&c3f, l3);
    __syncthreads();
    if (threadIdx.x == 0) g_mask_mode = (c3f > 0) ? 2 : (c1 > 0 ? 0 : 1);
}

// LN over cF cols of x (stride xs); cols [cF,Kx) from tailsrc (stride cD).
// Writes split blocks: [hi | hi | lo].
template <bool TAIL>
__global__ void __launch_bounds__(256) ln_bf16_k(
    const float* __restrict__ x, int xs, const float* __restrict__ tailsrc,
    const float* __restrict__ gam, const float* __restrict__ bet,
    __nv_bfloat16* __restrict__ dst, int Kx, int kt3)
{
    const int row = blockIdx.x, tid = threadIdx.x;
    const float* xr = x + (size_t)row * xs;
    float s = 0.f, s2 = 0.f;
    for (int c = tid * 4; c < cF; c += 1024) {
        float4 v = *reinterpret_cast<const float4*>(xr + c);
        s += v.x + v.y + v.z + v.w;
        s2 += v.x * v.x + v.y * v.y + v.z * v.z + v.w * v.w;
    }
    #pragma unroll
    for (int o = 16; o; o >>= 1) {
        s += __shfl_xor_sync(0xffffffffu, s, o);
        s2 += __shfl_xor_sync(0xffffffffu, s2, o);
    }
    __shared__ float ws[8], ws2[8];
    const int warp = tid >> 5, lane = tid & 31;
    if (lane == 0) { ws[warp] = s; ws2[warp] = s2; }
    __syncthreads();
    if (tid == 0) {
        float a = 0.f, b2 = 0.f;
        #pragma unroll
        for (int w = 0; w < 8; w++) { a += ws[w]; b2 += ws2[w]; }
        ws[0] = a; ws2[0] = b2;
    }
    __syncthreads();
    const float mean = ws[0] * (1.f / cF);
    const float rstd = rsqrtf(ws2[0] * (1.f / cF) - mean * mean + 1e-5f);
    const int mt = row >> 7, r = row & 127;
    char* db = (char*)dst;
    for (int p = tid; p < (Kx >> 1); p += 256) {
        const int c = 2 * p;
        float a, b;
        if (c < cF) {
            a = (xr[c] - mean) * rstd * gam[c] + bet[c];
            b = (xr[c + 1] - mean) * rstd * gam[c + 1] + bet[c + 1];
        } else {
            a = TAIL ? tailsrc[(size_t)row * cD + c] : 0.f;
            b = TAIL ? tailsrc[(size_t)row * cD + c + 1] : 0.f;
        }
        uint32_t hi = packbf(a, b), lo = packbf(residf(a), residf(b));
        putA(db, mt, kt3, r, c, hi);
        putA(db, mt, kt3, r, Kx + c, hi);
        putA(db, mt, kt3, r, 2 * Kx + c, lo);
    }
}

__global__ void __launch_bounds__(256) conv_act_k(
    const float* __restrict__ x, int xs, __nv_bfloat16* __restrict__ dst, int Kx, int kt3)
{
    const int Kh = Kx >> 1;
    const size_t idx = (size_t)blockIdx.x * 256 + threadIdx.x;
    const int row = (int)(idx / Kh), c = 2 * (int)(idx % Kh);
    const float a = x[(size_t)row * xs + c], b = x[(size_t)row * xs + c + 1];
    uint32_t hi = packbf(a, b), lo = packbf(residf(a), residf(b));
    char* db = (char*)dst;
    const int mt = row >> 7, r = row & 127;
    putA(db, mt, kt3, r, c, hi);
    putA(db, mt, kt3, r, Kx + c, hi);
    putA(db, mt, kt3, r, 2 * Kx + c, lo);
}

// weights: [Whi | Wlo | Whi] split (pairs with A's [hi|hi|lo])
__global__ void __launch_bounds__(256) conv_w_k(
    const float* __restrict__ w, __nv_bfloat16* __restrict__ dst, int Kx, int kt3)
{
    const int Kh = Kx >> 1;
    const size_t idx = (size_t)blockIdx.x * 256 + threadIdx.x;
    const int row = (int)(idx / Kh), c = 2 * (int)(idx % Kh);
    const float a = w[(size_t)row * Kx + c], b = w[(size_t)row * Kx + c + 1];
    uint32_t hi = packbf(a, b), lo = packbf(residf(a), residf(b));
    char* db = (char*)dst;
    const int nt = row >> 7, r = row & 127;
    putA(db, nt, kt3, r, c, hi);
    putA(db, nt, kt3, r, Kx + c, lo);
    putA(db, nt, kt3, r, 2 * Kx + c, hi);
}

// mma.sync GEMM: C[M,Nc] = A'[M,K'] @ W'[Nc,K']^T; BM=128 BN=128 BK=64,
// 8 warps (4x2), warp tile 32x64, HMMA m16n8k16 bf16, 3-stage bulk pipeline.
constexpr int STG = 32768, SD0 = 1024, SMB = SD0 + 3 * STG;

template <bool RELU, bool ADD>
__global__ void __launch_bounds__(256, 2) gemm_mma(
    const __nv_bfloat16* __restrict__ Ab, const __nv_bfloat16* __restrict__ Wb,
    const float* __restrict__ bias, const float* __restrict__ addsrc,
    float* __restrict__ C, int ktiles, int Nc)
{
    extern __shared__ __align__(1024) char smem[];
    const uint32_t sb = smem_u32(smem);
    const int tid = threadIdx.x, warp = tid >> 5, lane = tid & 31;
    const int nt = blockIdx.x, mt = blockIdx.y;

    if (tid == 0) {
        #pragma unroll
        for (int s = 0; s < 3; s++) MBAR_INIT(sb + 8 * s, 1);
    }
    __syncthreads();

    const char* Ag = (const char*)Ab + (size_t)mt * ktiles * 16384;
    const char* Wg = (const char*)Wb + (size_t)nt * ktiles * 16384;

    if (tid == 0) {
        #pragma unroll
        for (int s = 0; s < 3; s++) {
            MBAR_EXPECT_TX(sb + 8 * s, 32768);
            bulk_g2s(sb + SD0 + s * STG, Ag + (size_t)s * 16384, 16384, sb + 8 * s);
            bulk_g2s(sb + SD0 + s * STG + 16384, Wg + (size_t)s * 16384, 16384, sb + 8 * s);
        }
    }

    const int m0w = (warp >> 1) << 5;                 // 0,32,64,96
    const int n0w = (warp & 1) << 6;                  // 0,64
    const int arow = m0w + (lane & 15);
    const uint32_t aoff0 = (uint32_t)arow << 7;
    const uint32_t axor = (uint32_t)(arow & 7) << 4;
    const uint32_t akh = (uint32_t)(lane >> 4) << 4;  // k-half byte
    const uint32_t boff0 = (uint32_t)(n0w + lane) << 7;
    const uint32_t bxor = (uint32_t)(lane & 7) << 4;

    float acc[2][8][4];
    #pragma unroll
    for (int i = 0; i < 2; i++)
        #pragma unroll
        for (int j = 0; j < 8; j++)
            #pragma unroll
            for (int q = 0; q < 4; q++) acc[i][j][q] = 0.f;

    int s = 0, ph = 0;
    #pragma unroll 1
    for (int kt = 0; kt < ktiles; kt++) {
        MBAR_WAIT(sb + 8 * s, ph);
        const uint32_t As = sb + SD0 + s * STG;
        const uint32_t Bs = As + 16384;
        #pragma unroll
        for (int kk = 0; kk < 4; kk++) {
            uint32_t a[2][4];
            const uint32_t kbA = ((kk << 5) | akh) ^ axor;
            #pragma unroll
            for (int im = 0; im < 2; im++) {
                uint32_t ad = As + aoff0 + (im << 11) + kbA;
                asm volatile("ldmatrix.sync.aligned.m8n8.x4.shared.b16 {%0,%1,%2,%3}, [%4];"
                    : "=r"(a[im][0]), "=r"(a[im][1]), "=r"(a[im][2]), "=r"(a[im][3]) : "r"(ad));
            }
            uint32_t b0[8], b1[8];
            #pragma unroll
            for (int q = 0; q < 2; q++) {
                uint32_t bd = Bs + boff0 + (q << 12);
                uint32_t k0 = (kk << 5) ^ bxor;
                uint32_t k1 = ((kk << 5) | 16) ^ bxor;
                asm volatile("ldmatrix.sync.aligned.m8n8.x4.shared.b16 {%0,%1,%2,%3}, [%4];"
                    : "=r"(b0[q*4+0]), "=r"(b0[q*4+1]), "=r"(b0[q*4+2]), "=r"(b0[q*4+3]) : "r"(bd + k0));
                asm volatile("ldmatrix.sync.aligned.m8n8.x4.shared.b16 {%0,%1,%2,%3}, [%4];"
                    : "=r"(b1[q*4+0]), "=r"(b1[q*4+1]), "=r"(b1[q*4+2]), "=r"(b1[q*4+3]) : "r"(bd + k1));
            }
            #pragma unroll
            for (int im = 0; im < 2; im++)
                #pragma unroll
                for (int ng = 0; ng < 8; ng++)
                    asm volatile("mma.sync.aligned.m16n8k16.row.col.f32.bf16.bf16.f32 "
                        "{%0,%1,%2,%3}, {%4,%5,%6,%7}, {%8,%9}, {%0,%1,%2,%3};"
                        : "+f"(acc[im][ng][0]), "+f"(acc[im][ng][1]),
                          "+f"(acc[im][ng][2]), "+f"(acc[im][ng][3])
                        : "r"(a[im][0]), "r"(a[im][1]), "r"(a[im][2]), "r"(a[im][3]),
                          "r"(b0[ng]), "r"(b1[ng]));
        }
        __syncthreads();
        if (tid == 0 && kt + 3 < ktiles) {
            MBAR_EXPECT_TX(sb + 8 * s, 32768);
            bulk_g2s(sb + SD0 + s * STG, Ag + (size_t)(kt + 3) * 16384, 16384, sb + 8 * s);
            bulk_g2s(sb + SD0 + s * STG + 16384, Wg + (size_t)(kt + 3) * 16384, 16384, sb + 8 * s);
        }
        if (++s == 3) { s = 0; ph ^= 1; }
    }

    const int rb = mt * 128 + m0w + (lane >> 2);
    const int cb = nt * 128 + n0w + ((lane & 3) << 1);
    #pragma unroll
    for (int im = 0; im < 2; im++) {
        #pragma unroll
        for (int ng = 0; ng < 8; ng++) {
            const int r0 = rb + im * 16, c = cb + ng * 8;
            const float bx = bias[c], by = bias[c + 1];
            float2 v0 = make_float2(acc[im][ng][0] + bx, acc[im][ng][1] + by);
            float2 v1 = make_float2(acc[im][ng][2] + bx, acc[im][ng][3] + by);
            if (RELU) {
                v0.x = fmaxf(v0.x, 0.f); v0.y = fmaxf(v0.y, 0.f);
                v1.x = fmaxf(v1.x, 0.f); v1.y = fmaxf(v1.y, 0.f);
            }
            if (ADD) {
                const float2 a0 = *(const float2*)(addsrc + (size_t)r0 * Nc + c);
                const float2 a1 = *(const float2*)(addsrc + (size_t)(r0 + 8) * Nc + c);
                v0.x += a0.x; v0.y += a0.y; v1.x += a1.x; v1.y += a1.y;
            }
            *(float2*)(C + (size_t)r0 * Nc + c) = v0;
            *(float2*)(C + (size_t)(r0 + 8) * Nc + c) = v1;
        }
    }
}

__global__ void __launch_bounds__(256) attn_k(
    const void* __restrict__ mask, const float* __restrict__ q,
    const float* __restrict__ kk, const float* __restrict__ vv,
    float* __restrict__ attn_out, float* __restrict__ upd)
{
    const int b = blockIdx.x;
    __shared__ float sd[cS][cN];
    __shared__ float smask[cS];
    const int tid = threadIdx.x;
    if (tid < cS) {
        const int mm = g_mask_mode;
        const int idx = b * cS + tid;
        bool mk;
        if (mm == 0)      mk = ((const unsigned char*)mask)[idx] != 0;
        else if (mm == 1) mk = ((const int*)mask)[idx] != 0;
        else              mk = ((const float*)mask)[idx] != 0.f;
        smask[tid] = mk ? 1.f : 0.f;
    }
    __syncthreads();
    const int warp = tid >> 5, lane = tid & 31;
    const float scale = rsqrtf((float)cD);
    for (int p = warp; p < cS * cN; p += 8) {
        const int i = p / cN, j = p % cN;
        const float* qr = q + (size_t)(b * cS + i) * cD;
        const float* kr = kk + (size_t)(b * cN + j) * cD;
        float sum = 0.f;
        for (int d = lane * 4; d < cD; d += 128) {
            float4 qa = *reinterpret_cast<const float4*>(qr + d);
            float4 ka = *reinterpret_cast<const float4*>(kr + d);
            sum += qa.x * ka.x + qa.y * ka.y + qa.z * ka.z + qa.w * ka.w;
        }
        #pragma unroll
        for (int o = 16; o; o >>= 1) sum += __shfl_xor_sync(0xffffffffu, sum, o);
        if (lane == 0) sd[i][j] = (smask[i] > 0.f) ? -INFINITY : sum * scale;
    }
    __syncthreads();
    if (tid < cN) {
        const int j = tid;
        float m = -INFINITY;
        #pragma unroll
        for (int i = 0; i < cS; i++) m = fmaxf(m, sd[i][j]);
        float e[cS], ssum = 0.f;
        #pragma unroll
        for (int i = 0; i < cS; i++) { e[i] = expf(sd[i][j] - m); ssum += e[i]; }
        const float inv = 1.f / ssum;
        #pragma unroll
        for (int i = 0; i < cS; i++) {
            const float a = e[i] * inv;
            sd[i][j] = a;
            attn_out[(size_t)(b * cS + i) * cN + j] = a;
        }
    }
    __syncthreads();
    for (int d = tid; d < cD; d += 256) {
        float acc[cS];
        #pragma unroll
        for (int i = 0; i < cS; i++) acc[i] = 0.f;
        for (int j = 0; j < cN; j++) {
            const float vj = vv[(size_t)(b * cN + j) * cD + d];
            #pragma unroll
            for (int i = 0; i < cS; i++) acc[i] = fmaf(sd[i][j], vj, acc[i]);
        }
        #pragma unroll
        for (int i = 0; i < cS; i++) upd[(size_t)(b * cS + i) * cD + d] = acc[i];
    }
}

__global__ void __launch_bounds__(256) gru_k(
    const float* __restrict__ gi, const float* __restrict__ gh,
    const float* __restrict__ h, float* __restrict__ hnew)
{
    const size_t idx = (size_t)blockIdx.x * 256 + threadIdx.x;
    const int row = (int)(idx / cF), f = (int)(idx % cF);
    const size_t o = (size_t)row * G3 + f;
    const float ir = gi[o], iz = gi[o + cF], inn = gi[o + 2 * cF];
    const float hr = gh[o], hz = gh[o + cF], hn = gh[o + 2 * cF];
    const float hp = h[(size_t)row * cF + f];
    const float r = 1.f / (1.f + expf(-(ir + hr)));
    const float z = 1.f / (1.f + expf(-(iz + hz)));
    const float n = tanhf(inn + r * hn);
    hnew[(size_t)row * cF + f] = (1.f - z) * n + z * hp;
}

__global__ void __launch_bounds__(256) init_h_k(const float* __restrict__ cand, float* __restrict__ h) {
    const size_t idx = (size_t)blockIdx.x * 256 + threadIdx.x;
    const int row = (int)(idx / cF), f = (int)(idx % cF);
    h[idx] = cand[(size_t)row * cD + f];
}
__global__ void __launch_bounds__(256) out_slots_k(
    const float* __restrict__ cand, const float* __restrict__ h, float* __restrict__ out) {
    const size_t idx = (size_t)blockIdx.x * 256 + threadIdx.x;
    const int row = (int)(idx / cD), c = (int)(idx % cD);
    out[idx] = (c < cF) ? h[(size_t)row * cF + c] : cand[idx];
}
__global__ void __launch_bounds__(256) out_attn_k(const float* __restrict__ attn, float* __restrict__ out) {
    const size_t idx = (size_t)blockIdx.x * 256 + threadIdx.x;
    out[(size_t)BSr * cD + idx] = attn[idx];
}

extern "C" void kernel_launch(void* const* d_in, const int* in_sizes, int n_in,
                              void* d_out, int out_size)
{
    const float* cand = (const float*)d_in[0];
    const float* pano = (const float*)d_in[1];
    const void* mask = d_in[2];
    const float* Wq = (const float*)d_in[3];
    const float* bq = (const float*)d_in[4];
    const float* Wk = (const float*)d_in[5];
    const float* bk = (const float*)d_in[6];
    const float* Wv = (const float*)d_in[7];
    const float* bv = (const float*)d_in[8];
    const float* W_ih = (const float*)d_in[9];
    const float* b_ih = (const float*)d_in[10];
    const float* W_hh = (const float*)d_in[11];
    const float* b_hh = (const float*)d_in[12];
    const float* W1 = (const float*)d_in[13];
    const float* b1 = (const float*)d_in[14];
    const float* W2 = (const float*)d_in[15];
    const float* b2 = (const float*)d_in[16];
    const float* ln_in_g = (const float*)d_in[17];
    const float* ln_in_b = (const float*)d_in[18];
    const float* ln_slots_g = (const float*)d_in[19];
    const float* ln_slots_b = (const float*)d_in[20];
    const float* ln_pre_g = (const float*)d_in[21];
    const float* ln_pre_b = (const float*)d_in[22];
    float* out = (float*)d_out;

    float *p_k, *p_v, *p_q, *p_upd, *p_gi, *p_gh, *p_h, *p_hnew, *p_hid, *p_attn;
    __nv_bfloat16 *b_pano, *b_s, *b_upd, *b_h, *b_pre, *b_hid;
    __nv_bfloat16 *b_wq, *b_wk, *b_wv, *b_wih, *b_whh, *b_w1, *b_w2;
    cudaGetSymbolAddress((void**)&p_k, g_k);
    cudaGetSymbolAddress((void**)&p_v, g_v);
    cudaGetSymbolAddress((void**)&p_q, g_q);
    cudaGetSymbolAddress((void**)&p_upd, g_upd);
    cudaGetSymbolAddress((void**)&p_gi, g_gi);
    cudaGetSymbolAddress((void**)&p_gh, g_gh);
    cudaGetSymbolAddress((void**)&p_h, g_h);
    cudaGetSymbolAddress((void**)&p_hnew, g_hnew);
    cudaGetSymbolAddress((void**)&p_hid, g_hid);
    cudaGetSymbolAddress((void**)&p_attn, g_attn);
    cudaGetSymbolAddress((void**)&b_pano, g_pano_b);
    cudaGetSymbolAddress((void**)&b_s, g_s_b);
    cudaGetSymbolAddress((void**)&b_upd, g_upd_b);
    cudaGetSymbolAddress((void**)&b_h, g_h_b);
    cudaGetSymbolAddress((void**)&b_pre, g_pre_b);
    cudaGetSymbolAddress((void**)&b_hid, g_hid_b);
    cudaGetSymbolAddress((void**)&b_wq, g_wq_b);
    cudaGetSymbolAddress((void**)&b_wk, g_wk_b);
    cudaGetSymbolAddress((void**)&b_wv, g_wv_b);
    cudaGetSymbolAddress((void**)&b_wih, g_wih_b);
    cudaGetSymbolAddress((void**)&b_whh, g_whh_b);
    cudaGetSymbolAddress((void**)&b_w1, g_w1_b);
    cudaGetSymbolAddress((void**)&b_w2, g_w2_b);

    cudaFuncSetAttribute(gemm_mma<false, false>, cudaFuncAttributeMaxDynamicSharedMemorySize, SMB);
    cudaFuncSetAttribute(gemm_mma<true, false>, cudaFuncAttributeMaxDynamicSharedMemorySize, SMB);
    cudaFuncSetAttribute(gemm_mma<false, true>, cudaFuncAttributeMaxDynamicSharedMemorySize, SMB);

    detect_mask_k<<<1, 256>>>((const unsigned char*)mask);

    // weight conversions
    conv_w_k<<<(2176 * 1088) / 256, 256>>>(Wq, b_wq, 2176, KTD);
    conv_w_k<<<(2176 * 1088) / 256, 256>>>(Wk, b_wk, 2176, KTD);
    conv_w_k<<<(2176 * 1088) / 256, 256>>>(Wv, b_wv, 2176, KTD);
    conv_w_k<<<(6144 * 1088) / 256, 256>>>(W_ih, b_wih, 2176, KTD);
    conv_w_k<<<(6144 * 1024) / 256, 256>>>(W_hh, b_whh, 2048, KTF);
    conv_w_k<<<(2176 * 1024) / 256, 256>>>(W1, b_w1, 2048, KTF);
    conv_w_k<<<(2048 * 1088) / 256, 256>>>(W2, b_w2, 2176, KTD);

    // pano LN -> split blocks; k,v projections
    ln_bf16_k<true><<<BNr, 256>>>(pano, cD, pano, ln_in_g, ln_in_b, b_pano, 2176, KTD);
    gemm_mma<false, false><<<dim3(17, 288), 256, SMB>>>(b_pano, b_wk, bk, nullptr, p_k, KTD, 2176);
    gemm_mma<false, false><<<dim3(17, 288), 256, SMB>>>(b_pano, b_wv, bv, nullptr, p_v, KTD, 2176);

    init_h_k<<<(BSr * cF) / 256, 256>>>(cand, p_h);

    for (int it = 0; it < 3; it++) {
        ln_bf16_k<true><<<BSr, 256>>>(p_h, cF, cand, ln_slots_g, ln_slots_b, b_s, 2176, KTD);
        gemm_mma<false, false><<<dim3(17, 80), 256, SMB>>>(b_s, b_wq, bq, nullptr, p_q, KTD, 2176);
        attn_k<<<cB, 256>>>(mask, p_q, p_k, p_v, p_attn, p_upd);
        conv_act_k<<<(BSr * 1088) / 256, 256>>>(p_upd, cD, b_upd, 2176, KTD);
        conv_act_k<<<(BSr * 1024) / 256, 256>>>(p_h, cF, b_h, 2048, KTF);
        gemm_mma<false, false><<<dim3(48, 80), 256, SMB>>>(b_upd, b_wih, b_ih, nullptr, p_gi, KTD, 6144);
        gemm_mma<false, false><<<dim3(48, 80), 256, SMB>>>(b_h, b_whh, b_hh, nullptr, p_gh, KTF, 6144);
        gru_k<<<(BSr * cF) / 256, 256>>>(p_gi, p_gh, p_h, p_hnew);
        ln_bf16_k<false><<<BSr, 256>>>(p_hnew, cF, nullptr, ln_pre_g, ln_pre_b, b_pre, 2048, KTF);
        gemm_mma<true, false><<<dim3(17, 80), 256, SMB>>>(b_pre, b_w1, b1, nullptr, p_hid, KTF, 2176);
        conv_act_k<<<(BSr * 1088) / 256, 256>>>(p_hid, cD, b_hid, 2176, KTD);
        gemm_mma<false, true><<<dim3(16, 80), 256, SMB>>>(b_hid, b_w2, b2, p_hnew, p_h, KTD, 2048);
    }

    out_slots_k<<<(BSr * cD) / 256, 256>>>(cand, p_h, out);
    out_attn_k<<<(BSr * cN) / 256, 256>>>(p_attn, out);
}